// round 10
// baseline (speedup 1.0000x reference)
#include <cuda_runtime.h>

#define QW   12
#define DIMS 4096
#define NT   128
#define V    32

typedef unsigned long long ull;

// Layout A: s = (t<<5) | k        (k: s-bits 0..4, lane: s5..9, warp: s10,11)
// Layout B: s = (t&31) | (k<<5) | ((t>>5)<<10)
// wire j <-> s-bit (11-j). Warp bits (s10,s11) = wires 1,0 in BOTH layouts.

__device__ __forceinline__ float2 cmulf(float2 a, float2 b) {
    return make_float2(fmaf(a.x, b.x, -a.y * b.y), fmaf(a.x, b.y, a.y * b.x));
}

// ---- packed f32x2 helpers (Blackwell FFMA2: halves issue slots) ----
__device__ __forceinline__ ull pk2(float x, float y) {
    ull r;
    asm("mov.b64 %0, {%1, %2};" : "=l"(r) : "r"(__float_as_uint(x)), "r"(__float_as_uint(y)));
    return r;
}
__device__ __forceinline__ void upk2(ull a, float& x, float& y) {
    unsigned int lo, hi;
    asm("mov.b64 {%0, %1}, %2;" : "=r"(lo), "=r"(hi) : "l"(a));
    x = __uint_as_float(lo); y = __uint_as_float(hi);
}
__device__ __forceinline__ ull fma2(ull a, ull b, ull c) {
    ull r; asm("fma.rn.f32x2 %0, %1, %2, %3;" : "=l"(r) : "l"(a), "l"(b), "l"(c)); return r;
}
__device__ __forceinline__ ull mul2(ull a, ull b) {
    ull r; asm("mul.rn.f32x2 %0, %1, %2;" : "=l"(r) : "l"(a), "l"(b)); return r;
}

struct Sm {
    ull    xch[DIMS];        // 32KB exchange / image buffer
    float2 tab[512];         // diag tables: 16 sign-variants x 32 k-entries
    float2 csT[2][6][12];
    float2 uvT[2][6][12];
    float  aS[2][6][12];
    float  ang[12];
    float  red[48];
    float  cwS[108];
    float  cbS[12];
    float  kinit[32];
};

template<int M>
__device__ __forceinline__ void ry_liftp(ull* amp, float2 uvv) {
    const ull U  = pk2(uvv.x, uvv.x);
    const ull Vv = pk2(uvv.y, uvv.y);
#pragma unroll
    for (int k = 0; k < V; k++) {
        if (!(k & M)) {
            ull a = amp[k], b = amp[k | M];
            a = fma2(U, b, a);
            b = fma2(Vv, a, b);
            a = fma2(U, b, a);
            amp[k] = a; amp[k | M] = b;
        }
    }
}

__device__ __forceinline__ void reduce12(Sm& sm, float* part, int t, int lane,
                                         float scale, bool addBias) {
#pragma unroll
    for (int j = 0; j < QW; j++) {
        float v = part[j];
        v += __shfl_down_sync(0xffffffffu, v, 16);
        v += __shfl_down_sync(0xffffffffu, v, 8);
        v += __shfl_down_sync(0xffffffffu, v, 4);
        v += __shfl_down_sync(0xffffffffu, v, 2);
        v += __shfl_down_sync(0xffffffffu, v, 1);
        if (lane == 0) sm.red[(t >> 5) * QW + j] = v;
    }
    __syncthreads();
    if (t < QW) {
        float v = sm.red[t] + sm.red[QW + t] + sm.red[2 * QW + t] + sm.red[3 * QW + t];
        v *= scale;
        if (addBias) v += sm.cbS[t];
        sm.ang[t] = v;
    }
    __syncthreads();
}

__global__ void __launch_bounds__(NT) qiddm_kernel(
    const float* __restrict__ x, const float* __restrict__ conv_w,
    const float* __restrict__ conv_b, const float* __restrict__ w1,
    const float* __restrict__ lin_w, const float* __restrict__ lin_b,
    float* __restrict__ out)
{
    __shared__ Sm sm;
    const int t    = threadIdx.x;
    const int lane = t & 31;
    const int wh   = (t >> 5) << 5;
    const int b    = blockIdx.x;

    // ---------------- weight tables ----------------
    for (int idx = t; idx < 144; idx += NT) {
        int n = idx / 72, r = idx % 72, g = r / 12, w = r % 12;
        int i = g >> 1, l = g & 1;
        int base = (((n * 3 + i) * 2 + l) * 12 + w) * 3;
        float th = w1[base + 1];
        float sv, cv; __sincosf(0.5f * th, &sv, &cv);
        sm.csT[n][g][w] = make_float2(cv, sv);
        sm.uvT[n][g][w] = make_float2(-__tanf(0.25f * th), sv);
        float a = w1[base + 0];
        if (g > 0) {
            int ip = (g - 1) >> 1, lp = (g - 1) & 1;
            a += w1[(((n * 3 + ip) * 2 + lp) * 12 + w) * 3 + 2];
        }
        sm.aS[n][g][w] = a;
    }
    if (t < 108) sm.cwS[t] = conv_w[t];
    if (t < 12)  sm.cbS[t] = conv_b[t];

    float* img = (float*)sm.xch;
    const float* xb = x + (size_t)b * 1024;
    for (int i = t; i < 1024; i += NT) img[i] = xb[i];
    __syncthreads();

    // ---------------- conv 3x3 s2 p1 + global avg pool ----------------
    {
        float acc[QW];
#pragma unroll
        for (int c = 0; c < QW; c++) acc[c] = 0.f;
        for (int pos = t; pos < 256; pos += NT) {
            int oh = pos >> 4, ow = pos & 15;
#pragma unroll
            for (int kh = 0; kh < 3; kh++) {
                int r2 = 2 * oh + kh - 1;
                if ((unsigned)r2 < 32u) {
#pragma unroll
                    for (int kw = 0; kw < 3; kw++) {
                        int c2 = 2 * ow + kw - 1;
                        if ((unsigned)c2 < 32u) {
                            float v = img[r2 * 32 + c2];
#pragma unroll
                            for (int c = 0; c < QW; c++)
                                acc[c] = fmaf(sm.cwS[c * 9 + kh * 3 + kw], v, acc[c]);
                        }
                    }
                }
            }
        }
        __syncthreads();
        reduce12(sm, acc, t, lane, 1.f / 256.f, true);
    }

    // ---------------- circuit blocks ----------------
    ull amp[V];
    for (int n = 0; n < 2; n++) {
        // g=0 skipped: diag on |0> = global phase; 12 RYs on |0> = real product state (layout A)
        const float2* cs0 = sm.csT[n][0];
        if (t < 32) {
            float p = 1.f;
#pragma unroll
            for (int i = 0; i < 5; i++) p *= ((t >> i) & 1) ? cs0[11 - i].y : cs0[11 - i].x;
            sm.kinit[t] = p;
        }
        __syncthreads();
        float tpp = 1.f;
#pragma unroll
        for (int i = 0; i < 7; i++) tpp *= ((t >> i) & 1) ? cs0[6 - i].y : cs0[6 - i].x;
#pragma unroll
        for (int k = 0; k < V; k++) amp[k] = pk2(tpp * sm.kinit[k], 0.f);

        for (int g = 1; g < 6; g++) {
            const bool layA = (g & 1);           // diag layout: A for g odd, B for g even
            const int  r    = layA ? 1 : 2;      // CZ ring range of previous sublayer
            const bool addI = ((g & 1) == 0);    // enc folded at g = 2, 4
            const float* aSp = sm.aS[n][g];

            // ---- build sign-folded diag table ----
            const int nent = (r == 1) ? 128 : 512;
            for (int idx = t; idx < nent; idx += NT) {
                int v = idx >> 5, k = idx & 31;
                float ph = 0.f;
#pragma unroll
                for (int i = 0; i < 5; i++) {
                    int w = layA ? (11 - i) : (6 - i);
                    float a = aSp[w] + (addI ? sm.ang[w] : 0.f);
                    ph += a * ((float)((k >> i) & 1) - 0.5f);
                }
                int par;
                if (r == 1)
                    par = __popc(k & (k >> 1) & 0xF) ^ ((v & (k >> 4)) & 1) ^ (((v >> 1) & k) & 1);
                else
                    par = __popc(k & (k >> 2) & 0x7) ^ ((v & k) & 1) ^ (((v >> 1) & (k >> 1)) & 1)
                        ^ (((v >> 2) & (k >> 3)) & 1) ^ (((v >> 3) & (k >> 4)) & 1);
                float sv, cv; __sincosf(ph, &sv, &cv);
                float sg = (par & 1) ? -1.f : 1.f;
                sm.tab[idx] = make_float2(cv * sg, sv * sg);
            }

            // ---- per-thread phase + CZ t-internal sign + variant index ----
            float pt = 0.f;
            int ptpar, vv;
            if (layA) {
#pragma unroll
                for (int i = 0; i < 7; i++)
                    pt += (aSp[6 - i] + (addI ? sm.ang[6 - i] : 0.f)) * ((float)((t >> i) & 1) - 0.5f);
                ptpar = __popc(t & (t >> 1) & 0x3F);
                vv    = (t & 1) | (((t >> 6) & 1) << 1);
            } else {
#pragma unroll
                for (int i = 0; i < 5; i++)
                    pt += (aSp[11 - i] + (addI ? sm.ang[11 - i] : 0.f)) * ((float)((t >> i) & 1) - 0.5f);
                pt += (aSp[1] + (addI ? sm.ang[1] : 0.f)) * ((float)((t >> 5) & 1) - 0.5f);
                pt += (aSp[0] + (addI ? sm.ang[0] : 0.f)) * ((float)((t >> 6) & 1) - 0.5f);
                ptpar = __popc(t & (t >> 2) & 0x7) ^ (((t >> 5) & t) & 1) ^ (((t >> 6) & (t >> 1)) & 1);
                vv    = ((t >> 3) & 1) | (((t >> 4) & 1) << 1) | (((t >> 5) & 1) << 2) | (((t >> 6) & 1) << 3);
            }
            float sv, cv; __sincosf(pt, &sv, &cv);
            if (ptpar & 1) { sv = -sv; cv = -cv; }
            const float2 et = make_float2(cv, sv);
            __syncthreads();   // sync1: tab ready; also guards prior radix reads vs transpose stores

            // ---- apply diagonal (scalar d, packed apply) ----
            const float2* tb = &sm.tab[vv << 5];
            if (g == 1) {  // state still real after product init
#pragma unroll
                for (int k = 0; k < V; k++) {
                    float2 d = cmulf(et, tb[k]);
                    float ax, ay; upk2(amp[k], ax, ay);
                    amp[k] = pk2(ax * d.x, ax * d.y);
                }
            } else {
#pragma unroll
                for (int k = 0; k < V; k++) {
                    float2 d = cmulf(et, tb[k]);
                    float ax, ay; upk2(amp[k], ax, ay);
                    ull rr = mul2(amp[k], pk2(d.x, d.x));
                    amp[k] = fma2(pk2(ay, ax), pk2(-d.y, d.y), rr);
                }
            }

            // ---- locals set 1 (current k-bits) ----
            const float2* uv = sm.uvT[n][g];
            if (layA) {
                ry_liftp<1 >(amp, uv[11]); ry_liftp<2 >(amp, uv[10]); ry_liftp<4 >(amp, uv[9]);
                ry_liftp<8 >(amp, uv[8]);  ry_liftp<16>(amp, uv[7]);
            } else {
                ry_liftp<1 >(amp, uv[6]);  ry_liftp<2 >(amp, uv[5]);  ry_liftp<4 >(amp, uv[4]);
                ry_liftp<8 >(amp, uv[3]);  ry_liftp<16>(amp, uv[2]);
            }

            // ---- smem transpose: swap k-bits <-> lane-bits (XOR swizzle, conflict-free) ----
            if (layA) {  // A -> B
#pragma unroll
                for (int k = 0; k < V; k++) sm.xch[t * 32 + (k ^ lane)] = amp[k];
                __syncthreads();
#pragma unroll
                for (int k = 0; k < V; k++) amp[k] = sm.xch[(k + wh) * 32 + (lane ^ k)];
            } else {     // B -> A
#pragma unroll
                for (int k = 0; k < V; k++) sm.xch[(k + wh) * 32 + (lane ^ k)] = amp[k];
                __syncthreads();
#pragma unroll
                for (int k = 0; k < V; k++) amp[k] = sm.xch[t * 32 + (k ^ lane)];
            }
            __syncthreads();

            // ---- locals set 2 (new k-bits) ----
            if (layA) {
                ry_liftp<1 >(amp, uv[6]);  ry_liftp<2 >(amp, uv[5]);  ry_liftp<4 >(amp, uv[4]);
                ry_liftp<8 >(amp, uv[3]);  ry_liftp<16>(amp, uv[2]);
            } else {
                ry_liftp<1 >(amp, uv[11]); ry_liftp<2 >(amp, uv[10]); ry_liftp<4 >(amp, uv[9]);
                ry_liftp<8 >(amp, uv[8]);  ry_liftp<16>(amp, uv[7]);
            }

            // ---- fused radix-4 warp gate (s10 = wire 1, s11 = wire 0), packed ----
            {
                const float2 cA = sm.csT[n][g][1];
                const float2 cB = sm.csT[n][g][0];
                const float s1e = (t & 32) ? cA.y : -cA.y;
                const float s2e = (t & 64) ? cB.y : -cB.y;
                const ull WS = pk2(cA.x * cB.x, cA.x * cB.x);
                const ull WA = pk2(s1e * cB.x,  s1e * cB.x);
                const ull WB = pk2(cA.x * s2e,  cA.x * s2e);
                const ull WC = pk2(s1e * s2e,   s1e * s2e);
                const int tA = t ^ 32, tB = t ^ 64, tC = t ^ 96;
#pragma unroll
                for (int k = 0; k < V; k++) sm.xch[k * NT + t] = amp[k];
                __syncthreads();   // sync2
#pragma unroll
                for (int k = 0; k < V; k++) {
                    ull o1 = sm.xch[k * NT + tA];
                    ull o2 = sm.xch[k * NT + tB];
                    ull o3 = sm.xch[k * NT + tC];
                    ull rr = mul2(amp[k], WS);
                    rr = fma2(WA, o1, rr);
                    rr = fma2(WB, o2, rr);
                    rr = fma2(WC, o3, rr);
                    amp[k] = rr;
                }
            }
        }

        // ---- measurement (state in layout B; trailing diag/CZ drop out) ----
        {
            float S = 0.f, q0 = 0.f, q1 = 0.f, q2 = 0.f, q3 = 0.f, q4 = 0.f;
#pragma unroll
            for (int k = 0; k < V; k++) {
                float ax, ay; upk2(amp[k], ax, ay);
                float pr = fmaf(ax, ax, ay * ay);
                S += pr;
                q0 += (k & 1)  ? -pr : pr;
                q1 += (k & 2)  ? -pr : pr;
                q2 += (k & 4)  ? -pr : pr;
                q3 += (k & 8)  ? -pr : pr;
                q4 += (k & 16) ? -pr : pr;
            }
            float part[QW];
            part[6] = q0; part[5] = q1; part[4] = q2; part[3] = q3; part[2] = q4;
#pragma unroll
            for (int i = 0; i < 5; i++) part[11 - i] = ((t >> i) & 1) ? -S : S;
            part[1] = ((t >> 5) & 1) ? -S : S;
            part[0] = ((t >> 6) & 1) ? -S : S;
            __syncthreads();
            reduce12(sm, part, t, lane, 1.f, false);
        }
    }

    // ---------------- linear head ----------------
    for (int m = t; m < 1024; m += NT) {
        float acc = lin_b[m];
#pragma unroll
        for (int j = 0; j < QW; j++) acc = fmaf(sm.ang[j], lin_w[m * 12 + j], acc);
        out[(size_t)b * 1024 + m] = acc;
    }
}

extern "C" void kernel_launch(void* const* d_in, const int* in_sizes, int n_in,
                              void* d_out, int out_size) {
    const float* x      = (const float*)d_in[0];
    const float* conv_w = (const float*)d_in[1];
    const float* conv_b = (const float*)d_in[2];
    const float* w1     = (const float*)d_in[3];
    const float* lin_w  = (const float*)d_in[4];
    const float* lin_b  = (const float*)d_in[5];
    float* out = (float*)d_out;
    int B = in_sizes[0] / 1024;
    qiddm_kernel<<<B, NT>>>(x, conv_w, conv_b, w1, lin_w, lin_b, out);
}

// round 11
// speedup vs baseline: 1.0381x; 1.0381x over previous
#include <cuda_runtime.h>

#define QW   12
#define DIMS 4096
#define NT   128
#define V    32

// s (12 bits): per-group entry layout gives s-bit positions of k bits (5, register),
// lane bits (5), warp bits (2).  wire j <-> s-bit (11-j).
// Group: diag -> 5 local gates (K) -> T1 (k<->lane, intra-warp) -> 5 local gates (old L)
//        -> T2 (k0,k1 <-> warp bits, cross-warp) -> 2 local gates (old W).

__host__ __device__ constexpr int eKc(int g, int i) {
    return g == 1 ? i
         : g == 2 ? (i == 0 ? 10 : i == 1 ? 11 : 5 + i)
         : g == 3 ? (i < 2 ? 5 + i : i)
         : g == 4 ? (i < 2 ? i : 5 + i)
         :          (i == 0 ? 10 : i == 1 ? 11 : i);
}
__host__ __device__ constexpr int eLc(int g, int i) { return g == 1 ? 5 + i : eKc(g - 1, i); }
__host__ __device__ constexpr int eWc(int g, int i) {
    return (g == 1 || g == 4) ? 10 + i : (g == 3 ? i : 5 + i);
}

__device__ __forceinline__ float2 cmulf(float2 a, float2 b) {
    return make_float2(fmaf(a.x, b.x, -a.y * b.y), fmaf(a.x, b.y, a.y * b.x));
}
__device__ __forceinline__ int rotl12(int s, int r) {
    return ((s << r) | (s >> (12 - r))) & 0xFFF;
}

struct Sm {
    float2 buf[DIMS];        // 32KB: T1/T2 exchange + image buffer
    float2 tab[512];         // 16 variants x 32 k-entries
    float2 csT[2][12];       // g=0 init coefficients
    float2 uvT[2][6][12];    // lifting coeffs
    float  aS[2][6][12];
    float  ang[12];
    float  red[48];
    float  cwS[108];
    float  cbS[12];
    float  kinit[32];
};

template<int M>
__device__ __forceinline__ void ry_lift(float2* amp, float2 uv) {
    const float u = uv.x, v = uv.y;
#pragma unroll
    for (int k = 0; k < V; k++) {
        if (!(k & M)) {
            float2 a = amp[k], b = amp[k | M];
            a.x = fmaf(u, b.x, a.x); a.y = fmaf(u, b.y, a.y);
            b.x = fmaf(v, a.x, b.x); b.y = fmaf(v, a.y, b.y);
            a.x = fmaf(u, b.x, a.x); a.y = fmaf(u, b.y, a.y);
            amp[k] = a; amp[k | M] = b;
        }
    }
}

__device__ __forceinline__ void reduce12(Sm& sm, float* part, int t, int lane,
                                         float scale, bool addBias) {
#pragma unroll
    for (int j = 0; j < QW; j++) {
        float v = part[j];
        v += __shfl_down_sync(0xffffffffu, v, 16);
        v += __shfl_down_sync(0xffffffffu, v, 8);
        v += __shfl_down_sync(0xffffffffu, v, 4);
        v += __shfl_down_sync(0xffffffffu, v, 2);
        v += __shfl_down_sync(0xffffffffu, v, 1);
        if (lane == 0) sm.red[(t >> 5) * QW + j] = v;
    }
    __syncthreads();
    if (t < QW) {
        float v = sm.red[t] + sm.red[QW + t] + sm.red[2 * QW + t] + sm.red[3 * QW + t];
        v *= scale;
        if (addBias) v += sm.cbS[t];
        sm.ang[t] = v;
    }
    __syncthreads();
}

template<int G, int R, bool ADDI, bool FIRST>
__device__ __forceinline__ void do_group(Sm& sm, float2* amp, const float* aSp,
                                         const float2* uv, int t) {
    const int lane = t & 31;
    const int w    = t >> 5;
    const int wh   = w << 5;

    // ---- tab build: 512 entries; k = t&31 fixed per thread -> ONE sincos ----
    {
        const int k = t & 31;
        float ph = 0.f;
        int sBk = 0;
#pragma unroll
        for (int i = 0; i < 5; i++) {
            const int wi = 11 - eKc(G, i);
            float a = aSp[wi] + (ADDI ? sm.ang[wi] : 0.f);
            ph += a * ((float)((k >> i) & 1) - 0.5f);
            sBk |= ((k >> i) & 1) << eKc(G, i);
        }
        const int kkpar = __popc(sBk & rotl12(sBk, R)) & 1;
        float sv, cv; __sincosf(ph, &sv, &cv);
        const int vbase = t >> 5;   // 0..3
#pragma unroll
        for (int j = 0; j < 4; j++) {
            int v = vbase + 4 * j;
            int sg = kkpar ^ ((0x6996 >> (k & v)) & 1);   // v<16, k&v<16
            sm.tab[v * 32 + k] = sg ? make_float2(-cv, -sv) : make_float2(cv, sv);
        }
    }

    // ---- per-thread phase, tt parity, cross mask ----
    float ph = 0.f; int sBt = 0;
#pragma unroll
    for (int i = 0; i < 5; i++) {
        const int wi = 11 - eLc(G, i);
        float a = aSp[wi] + (ADDI ? sm.ang[wi] : 0.f);
        int bit = (t >> i) & 1;
        ph += a * ((float)bit - 0.5f);
        sBt |= bit << eLc(G, i);
    }
#pragma unroll
    for (int i = 0; i < 2; i++) {
        const int wi = 11 - eWc(G, i);
        float a = aSp[wi] + (ADDI ? sm.ang[wi] : 0.f);
        int bit = (t >> (5 + i)) & 1;
        ph += a * ((float)bit - 0.5f);
        sBt |= bit << eWc(G, i);
    }
    const int ptt = __popc(sBt & rotl12(sBt, R)) & 1;
    int c = 0;
#pragma unroll
    for (int i = 0; i < 5; i++) {
        const int p1 = (eKc(G, i) + R) % 12;
        const int p2 = (eKc(G, i) + 12 - R) % 12;
        c |= (((sBt >> p1) ^ (sBt >> p2)) & 1) << i;
    }
    float sv, cv; __sincosf(ph, &sv, &cv);
    if (ptt) { sv = -sv; cv = -cv; }
    const float2 et  = make_float2(cv, sv);
    const float2 eHi = (c & 16) ? make_float2(-cv, -sv) : et;
    __syncthreads();   // sync1: tab ready; fences prev group's T2 reads of buf

    // ---- diagonal ----
    const float2* tb = &sm.tab[(c & 15) << 5];
#pragma unroll
    for (int k = 0; k < V; k++) {
        float2 d = cmulf((k < 16) ? et : eHi, tb[k]);
        if (FIRST) {
            float ax = amp[k].x;
            amp[k] = make_float2(ax * d.x, ax * d.y);
        } else {
            amp[k] = cmulf(amp[k], d);
        }
    }

    // ---- stage 1: 5 gates on current k bits ----
    ry_lift<1 >(amp, uv[11 - eKc(G, 0)]);
    ry_lift<2 >(amp, uv[11 - eKc(G, 1)]);
    ry_lift<4 >(amp, uv[11 - eKc(G, 2)]);
    ry_lift<8 >(amp, uv[11 - eKc(G, 3)]);
    ry_lift<16>(amp, uv[11 - eKc(G, 4)]);

    // ---- T1: intra-warp k <-> lane transpose (warp-private 1024-entry block) ----
#pragma unroll
    for (int k = 0; k < V; k++) sm.buf[t * 32 + (k ^ lane)] = amp[k];
    __syncwarp();
#pragma unroll
    for (int k = 0; k < V; k++) amp[k] = sm.buf[(k + wh) * 32 + (lane ^ k)];
    __syncwarp();

    // ---- stage 2: 5 gates on new k bits (old lane bits) ----
    ry_lift<1 >(amp, uv[11 - eLc(G, 0)]);
    ry_lift<2 >(amp, uv[11 - eLc(G, 1)]);
    ry_lift<4 >(amp, uv[11 - eLc(G, 2)]);
    ry_lift<8 >(amp, uv[11 - eLc(G, 3)]);
    ry_lift<16>(amp, uv[11 - eLc(G, 4)]);

    // ---- T2: cross-warp swap k0,k1 <-> warp bits ----
#pragma unroll
    for (int k = 0; k < V; k++) sm.buf[t * 32 + (k ^ lane)] = amp[k];
    __syncthreads();   // sync2
#pragma unroll
    for (int k = 0; k < V; k++) {
        const int srcw = k & 3;
        const int srck = w | (k & 28);
        amp[k] = sm.buf[srcw * 1024 + lane * 32 + (srck ^ lane)];
    }

    // ---- stage 3: 2 gates on new k0,k1 (old warp bits) ----
    ry_lift<1>(amp, uv[11 - eWc(G, 0)]);
    ry_lift<2>(amp, uv[11 - eWc(G, 1)]);
}

__global__ void __launch_bounds__(NT) qiddm_kernel(
    const float* __restrict__ x, const float* __restrict__ conv_w,
    const float* __restrict__ conv_b, const float* __restrict__ w1,
    const float* __restrict__ lin_w, const float* __restrict__ lin_b,
    float* __restrict__ out)
{
    __shared__ Sm sm;
    const int t    = threadIdx.x;
    const int lane = t & 31;
    const int b    = blockIdx.x;

    // ---------------- weight tables ----------------
    for (int idx = t; idx < 144; idx += NT) {
        int n = idx / 72, r = idx % 72, g = r / 12, w = r % 12;
        int i = g >> 1, l = g & 1;
        int base = (((n * 3 + i) * 2 + l) * 12 + w) * 3;
        float th = w1[base + 1];
        float sv, cv; __sincosf(0.5f * th, &sv, &cv);
        if (g == 0) sm.csT[n][w] = make_float2(cv, sv);
        sm.uvT[n][g][w] = make_float2(-__tanf(0.25f * th), sv);
        float a = w1[base + 0];
        if (g > 0) {
            int ip = (g - 1) >> 1, lp = (g - 1) & 1;
            a += w1[(((n * 3 + ip) * 2 + lp) * 12 + w) * 3 + 2];
        }
        sm.aS[n][g][w] = a;
    }
    if (t < 108) sm.cwS[t] = conv_w[t];
    if (t < 12)  sm.cbS[t] = conv_b[t];

    float* img = (float*)sm.buf;
    const float* xb = x + (size_t)b * 1024;
    for (int i = t; i < 1024; i += NT) img[i] = xb[i];
    __syncthreads();

    // ---------------- conv 3x3 s2 p1 + global avg pool ----------------
    {
        float acc[QW];
#pragma unroll
        for (int c = 0; c < QW; c++) acc[c] = 0.f;
        for (int pos = t; pos < 256; pos += NT) {
            int oh = pos >> 4, ow = pos & 15;
#pragma unroll
            for (int kh = 0; kh < 3; kh++) {
                int r2 = 2 * oh + kh - 1;
                if ((unsigned)r2 < 32u) {
#pragma unroll
                    for (int kw = 0; kw < 3; kw++) {
                        int c2 = 2 * ow + kw - 1;
                        if ((unsigned)c2 < 32u) {
                            float v = img[r2 * 32 + c2];
#pragma unroll
                            for (int c = 0; c < QW; c++)
                                acc[c] = fmaf(sm.cwS[c * 9 + kh * 3 + kw], v, acc[c]);
                        }
                    }
                }
            }
        }
        __syncthreads();
        reduce12(sm, acc, t, lane, 1.f / 256.f, true);
    }

    // ---------------- circuit blocks ----------------
    float2 amp[V];
    for (int n = 0; n < 2; n++) {
        // g=0 skipped: diag on |0> = global phase; 12 RYs on |0> = real product state (layout E1)
        const float2* cs0 = sm.csT[n];
        if (t < 32) {
            float p = 1.f;
#pragma unroll
            for (int i = 0; i < 5; i++) p *= ((t >> i) & 1) ? cs0[11 - i].y : cs0[11 - i].x;
            sm.kinit[t] = p;
        }
        __syncthreads();
        float tpp = 1.f;
#pragma unroll
        for (int i = 0; i < 7; i++) tpp *= ((t >> i) & 1) ? cs0[6 - i].y : cs0[6 - i].x;
#pragma unroll
        for (int k = 0; k < V; k++) amp[k] = make_float2(tpp * sm.kinit[k], 0.f);

        // groups g=1..5 ; R = CZ ring of prev sublayer ; enc folded at g=2,4
        do_group<1, 1, false, true >(sm, amp, sm.aS[n][1], sm.uvT[n][1], t);
        do_group<2, 2, true,  false>(sm, amp, sm.aS[n][2], sm.uvT[n][2], t);
        do_group<3, 1, false, false>(sm, amp, sm.aS[n][3], sm.uvT[n][3], t);
        do_group<4, 2, true,  false>(sm, amp, sm.aS[n][4], sm.uvT[n][4], t);
        do_group<5, 1, false, false>(sm, amp, sm.aS[n][5], sm.uvT[n][5], t);

        // ---- measurement (end-G5 layout): k bit i -> wire 6-i ;
        //      lane bits -> wires {1,0,9,8,7} ; warp bits -> wires {11,10} ----
        {
            float S = 0.f, q0 = 0.f, q1 = 0.f, q2 = 0.f, q3 = 0.f, q4 = 0.f;
#pragma unroll
            for (int k = 0; k < V; k++) {
                float pr = fmaf(amp[k].x, amp[k].x, amp[k].y * amp[k].y);
                S += pr;
                q0 += (k & 1)  ? -pr : pr;
                q1 += (k & 2)  ? -pr : pr;
                q2 += (k & 4)  ? -pr : pr;
                q3 += (k & 8)  ? -pr : pr;
                q4 += (k & 16) ? -pr : pr;
            }
            float part[QW];
            part[6] = q0; part[5] = q1; part[4] = q2; part[3] = q3; part[2] = q4;
            part[1]  = (t & 1)  ? -S : S;   // lane0 -> s10 -> wire 1
            part[0]  = (t & 2)  ? -S : S;   // lane1 -> s11 -> wire 0
            part[9]  = (t & 4)  ? -S : S;   // lane2 -> s2  -> wire 9
            part[8]  = (t & 8)  ? -S : S;   // lane3 -> s3  -> wire 8
            part[7]  = (t & 16) ? -S : S;   // lane4 -> s4  -> wire 7
            part[11] = (t & 32) ? -S : S;   // warp0 -> s0  -> wire 11
            part[10] = (t & 64) ? -S : S;   // warp1 -> s1  -> wire 10
            __syncthreads();
            reduce12(sm, part, t, lane, 1.f, false);
        }
    }

    // ---------------- linear head ----------------
    for (int m = t; m < 1024; m += NT) {
        float acc = lin_b[m];
#pragma unroll
        for (int j = 0; j < QW; j++) acc = fmaf(sm.ang[j], lin_w[m * 12 + j], acc);
        out[(size_t)b * 1024 + m] = acc;
    }
}

extern "C" void kernel_launch(void* const* d_in, const int* in_sizes, int n_in,
                              void* d_out, int out_size) {
    const float* x      = (const float*)d_in[0];
    const float* conv_w = (const float*)d_in[1];
    const float* conv_b = (const float*)d_in[2];
    const float* w1     = (const float*)d_in[3];
    const float* lin_w  = (const float*)d_in[4];
    const float* lin_b  = (const float*)d_in[5];
    float* out = (float*)d_out;
    int B = in_sizes[0] / 1024;
    qiddm_kernel<<<B, NT>>>(x, conv_w, conv_b, w1, lin_w, lin_b, out);
}

// round 12
// speedup vs baseline: 1.3059x; 1.2579x over previous
#include <cuda_runtime.h>

#define QW   12
#define DIMS 4096
#define NT   256      // 2 independent samples per CTA, 128 threads each
#define HT   128
#define V    32

// Per half-CTA (one sample), identical to the proven R2 layout:
// Layout A: s = (tl<<5) | k       (k: s0..4, lane: s5..9, half-warp bits: s10,11)
// Layout B: s = (tl&31) | (k<<5) | ((tl>>5)<<10)
// wire j <-> s-bit (11-j).

__device__ __forceinline__ float2 cmulf(float2 a, float2 b) {
    return make_float2(fmaf(a.x, b.x, -a.y * b.y), fmaf(a.x, b.y, a.y * b.x));
}

struct Sm {
    float2 xch[2][DIMS];       // 64KB: per-half exchange / image buffer
    float2 tab[2][512];        // per-half diag tables
    float2 csT[2][6][12];      // weights (shared by both halves)
    float2 uvT[2][6][12];
    float  aS[2][6][12];
    float  ang[2][12];
    float  red[2][48];
    float  cwS[108];
    float  cbS[12];
    float  kinit[2][32];
};

// named barrier per half: ids 1 and 2 (0 is __syncthreads)
#define HBAR(sub) asm volatile("bar.sync %0, 128;" :: "r"((sub) + 1) : "memory")

template<int M>
__device__ __forceinline__ void ry_lift(float2* amp, float2 uv) {
    const float u = uv.x, v = uv.y;
#pragma unroll
    for (int k = 0; k < V; k++) {
        if (!(k & M)) {
            float2 a = amp[k], b = amp[k | M];
            a.x = fmaf(u, b.x, a.x); a.y = fmaf(u, b.y, a.y);
            b.x = fmaf(v, a.x, b.x); b.y = fmaf(v, a.y, b.y);
            a.x = fmaf(u, b.x, a.x); a.y = fmaf(u, b.y, a.y);
            amp[k] = a; amp[k | M] = b;
        }
    }
}

__device__ __forceinline__ void reduce12(Sm& sm, float* part, int tl, int lane, int sub,
                                         float scale, bool addBias) {
#pragma unroll
    for (int j = 0; j < QW; j++) {
        float v = part[j];
        v += __shfl_down_sync(0xffffffffu, v, 16);
        v += __shfl_down_sync(0xffffffffu, v, 8);
        v += __shfl_down_sync(0xffffffffu, v, 4);
        v += __shfl_down_sync(0xffffffffu, v, 2);
        v += __shfl_down_sync(0xffffffffu, v, 1);
        if (lane == 0) sm.red[sub][(tl >> 5) * QW + j] = v;
    }
    HBAR(sub);
    if (tl < QW) {
        float v = sm.red[sub][tl] + sm.red[sub][QW + tl]
                + sm.red[sub][2 * QW + tl] + sm.red[sub][3 * QW + tl];
        v *= scale;
        if (addBias) v += sm.cbS[tl];
        sm.ang[sub][tl] = v;
    }
    HBAR(sub);
}

__global__ void __launch_bounds__(NT) qiddm_kernel(
    const float* __restrict__ x, const float* __restrict__ conv_w,
    const float* __restrict__ conv_b, const float* __restrict__ w1,
    const float* __restrict__ lin_w, const float* __restrict__ lin_b,
    float* __restrict__ out)
{
    extern __shared__ char smraw[];
    Sm& sm = *reinterpret_cast<Sm*>(smraw);
    const int t    = threadIdx.x;
    const int sub  = t >> 7;         // which sample half
    const int tl   = t & 127;        // thread within half
    const int lane = t & 31;
    const int wh   = (tl >> 5) << 5; // warp-in-half base
    const int b    = blockIdx.x * 2 + sub;
    float2* xc = sm.xch[sub];

    // ---------------- weight tables (whole CTA cooperates, once) ----------------
    for (int idx = t; idx < 144; idx += NT) {
        int n = idx / 72, r = idx % 72, g = r / 12, w = r % 12;
        int i = g >> 1, l = g & 1;
        int base = (((n * 3 + i) * 2 + l) * 12 + w) * 3;
        float th = w1[base + 1];
        float sv, cv; __sincosf(0.5f * th, &sv, &cv);
        sm.csT[n][g][w] = make_float2(cv, sv);
        sm.uvT[n][g][w] = make_float2(-__tanf(0.25f * th), sv);
        float a = w1[base + 0];
        if (g > 0) {
            int ip = (g - 1) >> 1, lp = (g - 1) & 1;
            a += w1[(((n * 3 + ip) * 2 + lp) * 12 + w) * 3 + 2];
        }
        sm.aS[n][g][w] = a;
    }
    if (t < 108) sm.cwS[t] = conv_w[t];
    if (t < 12)  sm.cbS[t] = conv_b[t];

    // each half loads its own image into its own buffer
    float* img = (float*)xc;
    const float* xb = x + (size_t)b * 1024;
    for (int i = tl; i < 1024; i += HT) img[i] = xb[i];
    __syncthreads();   // one CTA-wide barrier; halves decouple after this

    // ---------------- conv 3x3 s2 p1 + global avg pool ----------------
    {
        float acc[QW];
#pragma unroll
        for (int c = 0; c < QW; c++) acc[c] = 0.f;
        for (int pos = tl; pos < 256; pos += HT) {
            int oh = pos >> 4, ow = pos & 15;
#pragma unroll
            for (int kh = 0; kh < 3; kh++) {
                int r2 = 2 * oh + kh - 1;
                if ((unsigned)r2 < 32u) {
#pragma unroll
                    for (int kw = 0; kw < 3; kw++) {
                        int c2 = 2 * ow + kw - 1;
                        if ((unsigned)c2 < 32u) {
                            float v = img[r2 * 32 + c2];
#pragma unroll
                            for (int c = 0; c < QW; c++)
                                acc[c] = fmaf(sm.cwS[c * 9 + kh * 3 + kw], v, acc[c]);
                        }
                    }
                }
            }
        }
        HBAR(sub);
        reduce12(sm, acc, tl, lane, sub, 1.f / 256.f, true);
    }

    // ---------------- circuit blocks ----------------
    float2 amp[V];
    for (int n = 0; n < 2; n++) {
        // g=0 skipped: diag on |0> = global phase; 12 RYs on |0> = real product state (layout A)
        const float2* cs0 = sm.csT[n][0];
        if (tl < 32) {
            float p = 1.f;
#pragma unroll
            for (int i = 0; i < 5; i++) p *= ((tl >> i) & 1) ? cs0[11 - i].y : cs0[11 - i].x;
            sm.kinit[sub][tl] = p;
        }
        HBAR(sub);
        float tpp = 1.f;
#pragma unroll
        for (int i = 0; i < 7; i++) tpp *= ((tl >> i) & 1) ? cs0[6 - i].y : cs0[6 - i].x;
#pragma unroll
        for (int k = 0; k < V; k++) amp[k] = make_float2(tpp * sm.kinit[sub][k], 0.f);

        for (int g = 1; g < 6; g++) {
            const bool layA = (g & 1);           // diag layout: A for g odd, B for g even
            const int  r    = layA ? 1 : 2;      // CZ ring range of previous sublayer
            const bool addI = ((g & 1) == 0);    // enc folded at g = 2, 4
            const float* aSp = sm.aS[n][g];
            const float* angp = sm.ang[sub];

            // ---- build sign-folded diag table ----
            const int nent = (r == 1) ? 128 : 512;
            for (int idx = tl; idx < nent; idx += HT) {
                int v = idx >> 5, k = idx & 31;
                float ph = 0.f;
#pragma unroll
                for (int i = 0; i < 5; i++) {
                    int w = layA ? (11 - i) : (6 - i);
                    float a = aSp[w] + (addI ? angp[w] : 0.f);
                    ph += a * ((float)((k >> i) & 1) - 0.5f);
                }
                int par;
                if (r == 1)
                    par = __popc(k & (k >> 1) & 0xF) ^ ((v & (k >> 4)) & 1) ^ (((v >> 1) & k) & 1);
                else
                    par = __popc(k & (k >> 2) & 0x7) ^ ((v & k) & 1) ^ (((v >> 1) & (k >> 1)) & 1)
                        ^ (((v >> 2) & (k >> 3)) & 1) ^ (((v >> 3) & (k >> 4)) & 1);
                float sv, cv; __sincosf(ph, &sv, &cv);
                float sg = (par & 1) ? -1.f : 1.f;
                sm.tab[sub][idx] = make_float2(cv * sg, sv * sg);
            }

            // ---- per-thread phase + CZ t-internal sign + variant index ----
            float pt = 0.f;
            int ptpar, vv;
            if (layA) {
#pragma unroll
                for (int i = 0; i < 7; i++)
                    pt += (aSp[6 - i] + (addI ? angp[6 - i] : 0.f)) * ((float)((tl >> i) & 1) - 0.5f);
                ptpar = __popc(tl & (tl >> 1) & 0x3F);
                vv    = (tl & 1) | (((tl >> 6) & 1) << 1);
            } else {
#pragma unroll
                for (int i = 0; i < 5; i++)
                    pt += (aSp[11 - i] + (addI ? angp[11 - i] : 0.f)) * ((float)((tl >> i) & 1) - 0.5f);
                pt += (aSp[1] + (addI ? angp[1] : 0.f)) * ((float)((tl >> 5) & 1) - 0.5f);
                pt += (aSp[0] + (addI ? angp[0] : 0.f)) * ((float)((tl >> 6) & 1) - 0.5f);
                ptpar = __popc(tl & (tl >> 2) & 0x7) ^ (((tl >> 5) & tl) & 1) ^ (((tl >> 6) & (tl >> 1)) & 1);
                vv    = ((tl >> 3) & 1) | (((tl >> 4) & 1) << 1) | (((tl >> 5) & 1) << 2) | (((tl >> 6) & 1) << 3);
            }
            float sv, cv; __sincosf(pt, &sv, &cv);
            if (ptpar & 1) { sv = -sv; cv = -cv; }
            const float2 et = make_float2(cv, sv);
            HBAR(sub);   // sync1: tab ready; also fences prev radix reads vs transpose stores

            // ---- apply diagonal ----
            const float2* tb = &sm.tab[sub][vv << 5];
            if (g == 1) {  // state still real after product init
#pragma unroll
                for (int k = 0; k < V; k++) {
                    float2 d = cmulf(et, tb[k]);
                    amp[k] = make_float2(amp[k].x * d.x, amp[k].x * d.y);
                }
            } else {
#pragma unroll
                for (int k = 0; k < V; k++) amp[k] = cmulf(amp[k], cmulf(et, tb[k]));
            }

            // ---- locals set 1 (current k-bits) ----
            const float2* uv = sm.uvT[n][g];
            if (layA) {
                ry_lift<1 >(amp, uv[11]); ry_lift<2 >(amp, uv[10]); ry_lift<4 >(amp, uv[9]);
                ry_lift<8 >(amp, uv[8]);  ry_lift<16>(amp, uv[7]);
            } else {
                ry_lift<1 >(amp, uv[6]);  ry_lift<2 >(amp, uv[5]);  ry_lift<4 >(amp, uv[4]);
                ry_lift<8 >(amp, uv[3]);  ry_lift<16>(amp, uv[2]);
            }

            // ---- smem transpose: swap k-bits <-> lane-bits (XOR swizzle) ----
            if (layA) {  // A -> B
#pragma unroll
                for (int k = 0; k < V; k++) xc[tl * 32 + (k ^ lane)] = amp[k];
                HBAR(sub);
#pragma unroll
                for (int k = 0; k < V; k++) amp[k] = xc[(k + wh) * 32 + (lane ^ k)];
            } else {     // B -> A
#pragma unroll
                for (int k = 0; k < V; k++) xc[(k + wh) * 32 + (lane ^ k)] = amp[k];
                HBAR(sub);
#pragma unroll
                for (int k = 0; k < V; k++) amp[k] = xc[tl * 32 + (k ^ lane)];
            }
            HBAR(sub);

            // ---- locals set 2 (new k-bits) ----
            if (layA) {
                ry_lift<1 >(amp, uv[6]);  ry_lift<2 >(amp, uv[5]);  ry_lift<4 >(amp, uv[4]);
                ry_lift<8 >(amp, uv[3]);  ry_lift<16>(amp, uv[2]);
            } else {
                ry_lift<1 >(amp, uv[11]); ry_lift<2 >(amp, uv[10]); ry_lift<4 >(amp, uv[9]);
                ry_lift<8 >(amp, uv[8]);  ry_lift<16>(amp, uv[7]);
            }

            // ---- fused radix-4 half-warp gate (s10 = wire 1, s11 = wire 0) ----
            {
                const float2 cA = sm.csT[n][g][1];
                const float2 cB = sm.csT[n][g][0];
                const float s1e = (tl & 32) ? cA.y : -cA.y;
                const float s2e = (tl & 64) ? cB.y : -cB.y;
                const float wS  = cA.x * cB.x;
                const float wA  = s1e * cB.x;
                const float wB  = cA.x * s2e;
                const float wC  = s1e * s2e;
                const int tA = tl ^ 32, tB = tl ^ 64, tC = tl ^ 96;
#pragma unroll
                for (int k = 0; k < V; k++) xc[k * HT + tl] = amp[k];
                HBAR(sub);   // sync2
#pragma unroll
                for (int k = 0; k < V; k++) {
                    float2 o1 = xc[k * HT + tA];
                    float2 o2 = xc[k * HT + tB];
                    float2 o3 = xc[k * HT + tC];
                    float ax = wS * amp[k].x, ay = wS * amp[k].y;
                    ax = fmaf(wA, o1.x, ax); ay = fmaf(wA, o1.y, ay);
                    ax = fmaf(wB, o2.x, ax); ay = fmaf(wB, o2.y, ay);
                    ax = fmaf(wC, o3.x, ax); ay = fmaf(wC, o3.y, ay);
                    amp[k] = make_float2(ax, ay);
                }
            }
        }

        // ---- measurement (state in layout B; trailing diag/CZ drop out) ----
        {
            float S = 0.f, q0 = 0.f, q1 = 0.f, q2 = 0.f, q3 = 0.f, q4 = 0.f;
#pragma unroll
            for (int k = 0; k < V; k++) {
                float pr = fmaf(amp[k].x, amp[k].x, amp[k].y * amp[k].y);
                S += pr;
                q0 += (k & 1)  ? -pr : pr;
                q1 += (k & 2)  ? -pr : pr;
                q2 += (k & 4)  ? -pr : pr;
                q3 += (k & 8)  ? -pr : pr;
                q4 += (k & 16) ? -pr : pr;
            }
            float part[QW];
            part[6] = q0; part[5] = q1; part[4] = q2; part[3] = q3; part[2] = q4;
#pragma unroll
            for (int i = 0; i < 5; i++) part[11 - i] = ((tl >> i) & 1) ? -S : S;
            part[1] = ((tl >> 5) & 1) ? -S : S;
            part[0] = ((tl >> 6) & 1) ? -S : S;
            HBAR(sub);
            reduce12(sm, part, tl, lane, sub, 1.f, false);
        }
    }

    // ---------------- linear head ----------------
    for (int m = tl; m < 1024; m += HT) {
        float acc = lin_b[m];
#pragma unroll
        for (int j = 0; j < QW; j++) acc = fmaf(sm.ang[sub][j], lin_w[m * 12 + j], acc);
        out[(size_t)b * 1024 + m] = acc;
    }
}

extern "C" void kernel_launch(void* const* d_in, const int* in_sizes, int n_in,
                              void* d_out, int out_size) {
    const float* x      = (const float*)d_in[0];
    const float* conv_w = (const float*)d_in[1];
    const float* conv_b = (const float*)d_in[2];
    const float* w1     = (const float*)d_in[3];
    const float* lin_w  = (const float*)d_in[4];
    const float* lin_b  = (const float*)d_in[5];
    float* out = (float*)d_out;
    int B = in_sizes[0] / 1024;
    cudaFuncSetAttribute(qiddm_kernel, cudaFuncAttributeMaxDynamicSharedMemorySize,
                         (int)sizeof(Sm));
    qiddm_kernel<<<B / 2, NT, sizeof(Sm)>>>(x, conv_w, conv_b, w1, lin_w, lin_b, out);
}

// round 13
// speedup vs baseline: 1.5087x; 1.1553x over previous
#include <cuda_runtime.h>

#define QW   12
#define DIMS 4096
#define NT   128
#define V    32

// Layout A: s = (t<<5) | k       (k: s0..4, lane: s5..9, warp bits: s10,11)
// Layout B: s = (t&31) | (k<<5) | ((t>>5)<<10)
// wire j <-> s-bit (11-j).

__device__ __forceinline__ float2 cmulf(float2 a, float2 b) {
    return make_float2(fmaf(a.x, b.x, -a.y * b.y), fmaf(a.x, b.y, a.y * b.x));
}

struct Sm {
    float2 xch[DIMS];        // 32KB exchange / image buffer
    float2 tab[512];
    float2 csT[2][6][12];
    float2 uvT[2][6][12];
    float  aS[2][6][12];
    float  ang[12];
    float  red[48];
    float  cwS[108];
    float  cbS[12];
    float  kinit[32];
};

// asm named barrier (id 1, all 128 threads) — part of the low-register recipe
#define HBAR() asm volatile("bar.sync 1, 128;" ::: "memory")

template<int M>
__device__ __forceinline__ void ry_lift(float2* amp, float2 uv) {
    const float u = uv.x, v = uv.y;
#pragma unroll
    for (int k = 0; k < V; k++) {
        if (!(k & M)) {
            float2 a = amp[k], b = amp[k | M];
            a.x = fmaf(u, b.x, a.x); a.y = fmaf(u, b.y, a.y);
            b.x = fmaf(v, a.x, b.x); b.y = fmaf(v, a.y, b.y);
            a.x = fmaf(u, b.x, a.x); a.y = fmaf(u, b.y, a.y);
            amp[k] = a; amp[k | M] = b;
        }
    }
}

__device__ __forceinline__ void reduce12(Sm& sm, float* part, int t, int lane,
                                         float scale, bool addBias) {
#pragma unroll
    for (int j = 0; j < QW; j++) {
        float v = part[j];
        v += __shfl_down_sync(0xffffffffu, v, 16);
        v += __shfl_down_sync(0xffffffffu, v, 8);
        v += __shfl_down_sync(0xffffffffu, v, 4);
        v += __shfl_down_sync(0xffffffffu, v, 2);
        v += __shfl_down_sync(0xffffffffu, v, 1);
        if (lane == 0) sm.red[(t >> 5) * QW + j] = v;
    }
    HBAR();
    if (t < QW) {
        float v = sm.red[t] + sm.red[QW + t] + sm.red[2 * QW + t] + sm.red[3 * QW + t];
        v *= scale;
        if (addBias) v += sm.cbS[t];
        sm.ang[t] = v;
    }
    HBAR();
}

__global__ void __launch_bounds__(NT, 3) qiddm_kernel(
    const float* __restrict__ x, const float* __restrict__ conv_w,
    const float* __restrict__ conv_b, const float* __restrict__ w1,
    const float* __restrict__ lin_w, const float* __restrict__ lin_b,
    float* __restrict__ out)
{
    extern __shared__ char smraw[];
    Sm& sm = *reinterpret_cast<Sm*>(smraw);
    const int t    = threadIdx.x;
    const int lane = t & 31;
    const int wh   = (t >> 5) << 5;
    const int b    = blockIdx.x;
    float2* xc = sm.xch;

    // ---------------- weight tables ----------------
    for (int idx = t; idx < 144; idx += NT) {
        int n = idx / 72, r = idx % 72, g = r / 12, w = r % 12;
        int i = g >> 1, l = g & 1;
        int base = (((n * 3 + i) * 2 + l) * 12 + w) * 3;
        float th = w1[base + 1];
        float sv, cv; __sincosf(0.5f * th, &sv, &cv);
        sm.csT[n][g][w] = make_float2(cv, sv);
        sm.uvT[n][g][w] = make_float2(-__tanf(0.25f * th), sv);
        float a = w1[base + 0];
        if (g > 0) {
            int ip = (g - 1) >> 1, lp = (g - 1) & 1;
            a += w1[(((n * 3 + ip) * 2 + lp) * 12 + w) * 3 + 2];
        }
        sm.aS[n][g][w] = a;
    }
    if (t < 108) sm.cwS[t] = conv_w[t];
    if (t < 12)  sm.cbS[t] = conv_b[t];

    float* img = (float*)xc;
    const float* xb = x + (size_t)b * 1024;
    for (int i = t; i < 1024; i += NT) img[i] = xb[i];
    __syncthreads();

    // ---------------- conv 3x3 s2 p1 + global avg pool ----------------
    {
        float acc[QW];
#pragma unroll
        for (int c = 0; c < QW; c++) acc[c] = 0.f;
        for (int pos = t; pos < 256; pos += NT) {
            int oh = pos >> 4, ow = pos & 15;
#pragma unroll
            for (int kh = 0; kh < 3; kh++) {
                int r2 = 2 * oh + kh - 1;
                if ((unsigned)r2 < 32u) {
#pragma unroll
                    for (int kw = 0; kw < 3; kw++) {
                        int c2 = 2 * ow + kw - 1;
                        if ((unsigned)c2 < 32u) {
                            float v = img[r2 * 32 + c2];
#pragma unroll
                            for (int c = 0; c < QW; c++)
                                acc[c] = fmaf(sm.cwS[c * 9 + kh * 3 + kw], v, acc[c]);
                        }
                    }
                }
            }
        }
        HBAR();
        reduce12(sm, acc, t, lane, 1.f / 256.f, true);
    }

    // ---------------- circuit blocks ----------------
    float2 amp[V];
    for (int n = 0; n < 2; n++) {
        // g=0 skipped: diag on |0> = global phase; 12 RYs on |0> = real product state (layout A)
        const float2* cs0 = sm.csT[n][0];
        if (t < 32) {
            float p = 1.f;
#pragma unroll
            for (int i = 0; i < 5; i++) p *= ((t >> i) & 1) ? cs0[11 - i].y : cs0[11 - i].x;
            sm.kinit[t] = p;
        }
        HBAR();
        float tpp = 1.f;
#pragma unroll
        for (int i = 0; i < 7; i++) tpp *= ((t >> i) & 1) ? cs0[6 - i].y : cs0[6 - i].x;
#pragma unroll
        for (int k = 0; k < V; k++) amp[k] = make_float2(tpp * sm.kinit[k], 0.f);

        for (int g = 1; g < 6; g++) {
            const bool layA = (g & 1);           // diag layout: A for g odd, B for g even
            const int  r    = layA ? 1 : 2;      // CZ ring range of previous sublayer
            const bool addI = ((g & 1) == 0);    // enc folded at g = 2, 4
            const float* aSp = sm.aS[n][g];
            const float* angp = sm.ang;

            // ---- build sign-folded diag table ----
            const int nent = (r == 1) ? 128 : 512;
            for (int idx = t; idx < nent; idx += NT) {
                int v = idx >> 5, k = idx & 31;
                float ph = 0.f;
#pragma unroll
                for (int i = 0; i < 5; i++) {
                    int w = layA ? (11 - i) : (6 - i);
                    float a = aSp[w] + (addI ? angp[w] : 0.f);
                    ph += a * ((float)((k >> i) & 1) - 0.5f);
                }
                int par;
                if (r == 1)
                    par = __popc(k & (k >> 1) & 0xF) ^ ((v & (k >> 4)) & 1) ^ (((v >> 1) & k) & 1);
                else
                    par = __popc(k & (k >> 2) & 0x7) ^ ((v & k) & 1) ^ (((v >> 1) & (k >> 1)) & 1)
                        ^ (((v >> 2) & (k >> 3)) & 1) ^ (((v >> 3) & (k >> 4)) & 1);
                float sv, cv; __sincosf(ph, &sv, &cv);
                float sg = (par & 1) ? -1.f : 1.f;
                sm.tab[idx] = make_float2(cv * sg, sv * sg);
            }

            // ---- per-thread phase + CZ t-internal sign + variant index ----
            float pt = 0.f;
            int ptpar, vv;
            if (layA) {
#pragma unroll
                for (int i = 0; i < 7; i++)
                    pt += (aSp[6 - i] + (addI ? angp[6 - i] : 0.f)) * ((float)((t >> i) & 1) - 0.5f);
                ptpar = __popc(t & (t >> 1) & 0x3F);
                vv    = (t & 1) | (((t >> 6) & 1) << 1);
            } else {
#pragma unroll
                for (int i = 0; i < 5; i++)
                    pt += (aSp[11 - i] + (addI ? angp[11 - i] : 0.f)) * ((float)((t >> i) & 1) - 0.5f);
                pt += (aSp[1] + (addI ? angp[1] : 0.f)) * ((float)((t >> 5) & 1) - 0.5f);
                pt += (aSp[0] + (addI ? angp[0] : 0.f)) * ((float)((t >> 6) & 1) - 0.5f);
                ptpar = __popc(t & (t >> 2) & 0x7) ^ (((t >> 5) & t) & 1) ^ (((t >> 6) & (t >> 1)) & 1);
                vv    = ((t >> 3) & 1) | (((t >> 4) & 1) << 1) | (((t >> 5) & 1) << 2) | (((t >> 6) & 1) << 3);
            }
            float sv, cv; __sincosf(pt, &sv, &cv);
            if (ptpar & 1) { sv = -sv; cv = -cv; }
            const float2 et = make_float2(cv, sv);
            HBAR();   // sync1: tab ready; also fences prev radix reads vs transpose stores

            // ---- apply diagonal ----
            const float2* tb = &sm.tab[vv << 5];
            if (g == 1) {  // state still real after product init
#pragma unroll
                for (int k = 0; k < V; k++) {
                    float2 d = cmulf(et, tb[k]);
                    amp[k] = make_float2(amp[k].x * d.x, amp[k].x * d.y);
                }
            } else {
#pragma unroll
                for (int k = 0; k < V; k++) amp[k] = cmulf(amp[k], cmulf(et, tb[k]));
            }

            // ---- locals set 1 (current k-bits) ----
            const float2* uv = sm.uvT[n][g];
            if (layA) {
                ry_lift<1 >(amp, uv[11]); ry_lift<2 >(amp, uv[10]); ry_lift<4 >(amp, uv[9]);
                ry_lift<8 >(amp, uv[8]);  ry_lift<16>(amp, uv[7]);
            } else {
                ry_lift<1 >(amp, uv[6]);  ry_lift<2 >(amp, uv[5]);  ry_lift<4 >(amp, uv[4]);
                ry_lift<8 >(amp, uv[3]);  ry_lift<16>(amp, uv[2]);
            }

            // ---- smem transpose: swap k-bits <-> lane-bits (XOR swizzle) ----
            if (layA) {  // A -> B
#pragma unroll
                for (int k = 0; k < V; k++) xc[t * 32 + (k ^ lane)] = amp[k];
                HBAR();
#pragma unroll
                for (int k = 0; k < V; k++) amp[k] = xc[(k + wh) * 32 + (lane ^ k)];
            } else {     // B -> A
#pragma unroll
                for (int k = 0; k < V; k++) xc[(k + wh) * 32 + (lane ^ k)] = amp[k];
                HBAR();
#pragma unroll
                for (int k = 0; k < V; k++) amp[k] = xc[t * 32 + (k ^ lane)];
            }
            HBAR();

            // ---- locals set 2 (new k-bits) ----
            if (layA) {
                ry_lift<1 >(amp, uv[6]);  ry_lift<2 >(amp, uv[5]);  ry_lift<4 >(amp, uv[4]);
                ry_lift<8 >(amp, uv[3]);  ry_lift<16>(amp, uv[2]);
            } else {
                ry_lift<1 >(amp, uv[11]); ry_lift<2 >(amp, uv[10]); ry_lift<4 >(amp, uv[9]);
                ry_lift<8 >(amp, uv[8]);  ry_lift<16>(amp, uv[7]);
            }

            // ---- fused radix-4 warp gate (s10 = wire 1, s11 = wire 0) ----
            {
                const float2 cA = sm.csT[n][g][1];
                const float2 cB = sm.csT[n][g][0];
                const float s1e = (t & 32) ? cA.y : -cA.y;
                const float s2e = (t & 64) ? cB.y : -cB.y;
                const float wS  = cA.x * cB.x;
                const float wA  = s1e * cB.x;
                const float wB  = cA.x * s2e;
                const float wC  = s1e * s2e;
                const int tA = t ^ 32, tB = t ^ 64, tC = t ^ 96;
#pragma unroll
                for (int k = 0; k < V; k++) xc[k * NT + t] = amp[k];
                HBAR();   // sync2
#pragma unroll
                for (int k = 0; k < V; k++) {
                    float2 o1 = xc[k * NT + tA];
                    float2 o2 = xc[k * NT + tB];
                    float2 o3 = xc[k * NT + tC];
                    float ax = wS * amp[k].x, ay = wS * amp[k].y;
                    ax = fmaf(wA, o1.x, ax); ay = fmaf(wA, o1.y, ay);
                    ax = fmaf(wB, o2.x, ax); ay = fmaf(wB, o2.y, ay);
                    ax = fmaf(wC, o3.x, ax); ay = fmaf(wC, o3.y, ay);
                    amp[k] = make_float2(ax, ay);
                }
            }
        }

        // ---- measurement (state in layout B; trailing diag/CZ drop out) ----
        {
            float S = 0.f, q0 = 0.f, q1 = 0.f, q2 = 0.f, q3 = 0.f, q4 = 0.f;
#pragma unroll
            for (int k = 0; k < V; k++) {
                float pr = fmaf(amp[k].x, amp[k].x, amp[k].y * amp[k].y);
                S += pr;
                q0 += (k & 1)  ? -pr : pr;
                q1 += (k & 2)  ? -pr : pr;
                q2 += (k & 4)  ? -pr : pr;
                q3 += (k & 8)  ? -pr : pr;
                q4 += (k & 16) ? -pr : pr;
            }
            float part[QW];
            part[6] = q0; part[5] = q1; part[4] = q2; part[3] = q3; part[2] = q4;
#pragma unroll
            for (int i = 0; i < 5; i++) part[11 - i] = ((t >> i) & 1) ? -S : S;
            part[1] = ((t >> 5) & 1) ? -S : S;
            part[0] = ((t >> 6) & 1) ? -S : S;
            HBAR();
            reduce12(sm, part, t, lane, 1.f, false);
        }
    }

    // ---------------- linear head ----------------
    for (int m = t; m < 1024; m += NT) {
        float acc = lin_b[m];
#pragma unroll
        for (int j = 0; j < QW; j++) acc = fmaf(sm.ang[j], lin_w[m * 12 + j], acc);
        out[(size_t)b * 1024 + m] = acc;
    }
}

extern "C" void kernel_launch(void* const* d_in, const int* in_sizes, int n_in,
                              void* d_out, int out_size) {
    const float* x      = (const float*)d_in[0];
    const float* conv_w = (const float*)d_in[1];
    const float* conv_b = (const float*)d_in[2];
    const float* w1     = (const float*)d_in[3];
    const float* lin_w  = (const float*)d_in[4];
    const float* lin_b  = (const float*)d_in[5];
    float* out = (float*)d_out;
    int B = in_sizes[0] / 1024;
    cudaFuncSetAttribute(qiddm_kernel, cudaFuncAttributeMaxDynamicSharedMemorySize,
                         (int)sizeof(Sm));
    qiddm_kernel<<<B, NT, sizeof(Sm)>>>(x, conv_w, conv_b, w1, lin_w, lin_b, out);
}